// round 5
// baseline (speedup 1.0000x reference)
#include <cuda_runtime.h>
#include <math.h>

#define NTHREADS 256
#define NW 8            // warps per block = probes per round
#define NCLS 1000
#define NPAD 1024
#define NT 800
#define TSTEP 0.00125f
#define TOL 0.01f

__global__ __launch_bounds__(NTHREADS)
void logit_compression_kernel(const float* __restrict__ logits,
                              float* __restrict__ out) {
    __shared__ float dsm[NPAD];      // d_j = fl(l_j - m), padded with -inf
    __shared__ float redm[NW];
    __shared__ float red1[NW], red6[NW], red12[NW];
    __shared__ float ctbuf[2][NW];
    __shared__ float bmax;
    __shared__ float bs1, bs6, bs12;

    const int tid  = threadIdx.x;
    const int lane = tid & 31;
    const int w    = tid >> 5;
    const int row  = blockIdx.x;
    const float* lrow = logits + row * NCLS;
    float* orow = out + row * NCLS;

    // ---- load row ----
    float r[4];
#pragma unroll
    for (int k = 0; k < 4; k++) {
        int idx = tid + k * NTHREADS;
        r[k] = (idx < NCLS) ? lrow[idx] : -INFINITY;
    }

    // ---- block max (exact) ----
    float mv = fmaxf(fmaxf(r[0], r[1]), fmaxf(r[2], r[3]));
#pragma unroll
    for (int o = 16; o > 0; o >>= 1) mv = fmaxf(mv, __shfl_xor_sync(0xffffffffu, mv, o));
    if (lane == 0) redm[w] = mv;
    __syncthreads();
    if (tid < 32) {
        float v = (tid < NW) ? redm[tid] : -INFINITY;
#pragma unroll
        for (int o = 4; o > 0; o >>= 1) v = fmaxf(v, __shfl_xor_sync(0xffffffffu, v, o));
        if (tid == 0) bmax = v;
    }
    __syncthreads();
    const float m = bmax;

    // ---- d -> smem; S1 (ACCURATE expf, reference-faithful) + S(6), S(12)
    //      (fast expf, prediction only) in one pass ----
    float s1 = 0.0f, s6 = 0.0f, s12 = 0.0f;
#pragma unroll
    for (int k = 0; k < 4; k++) {
        float dk = __fsub_rn(r[k], m);     // -inf for padding lanes
        dsm[tid + k * NTHREADS] = dk;
        s1  += expf(dk);                   // expf(-inf) == 0
        s6  += __expf(__fmul_rn(dk, 6.0f));
        s12 += __expf(__fmul_rn(dk, 12.0f));
    }
#pragma unroll
    for (int o = 16; o > 0; o >>= 1) {
        s1  += __shfl_xor_sync(0xffffffffu, s1, o);
        s6  += __shfl_xor_sync(0xffffffffu, s6, o);
        s12 += __shfl_xor_sync(0xffffffffu, s12, o);
    }
    if (lane == 0) { red1[w] = s1; red6[w] = s6; red12[w] = s12; }
    __syncthreads();
    if (tid < 32) {
        float v1 = (tid < NW) ? red1[tid]  : 0.0f;
        float v6 = (tid < NW) ? red6[tid]  : 0.0f;
        float vc = (tid < NW) ? red12[tid] : 0.0f;
#pragma unroll
        for (int o = 4; o > 0; o >>= 1) {
            v1 += __shfl_xor_sync(0xffffffffu, v1, o);
            v6 += __shfl_xor_sync(0xffffffffu, v6, o);
            vc += __shfl_xor_sync(0xffffffffu, vc, o);
        }
        if (tid == 0) { bs1 = v1; bs6 = v6; bs12 = vc; }
    }
    __syncthreads();                       // publishes sums AND dsm to all warps
    const float S1 = bs1, S6 = bs6, S12 = bs12;

    // ---- original confidence, bin, target confidence (reference rounding) ----
    const float conf = __fdiv_rn(1.0f, S1);
    int b = (conf >= (2.0f / 3.0f)) ? 2 : (conf >= (1.0f / 3.0f)) ? 1 : 0;
    const float BL  = (b == 0) ? 0.0f : (b == 1) ? (1.0f / 3.0f) : (2.0f / 3.0f);
    const float NBL = (b == 0) ? 0.8f : (b == 1) ? 0.86666666666f : 0.93333333333f;
    const float nc  = __fadd_rn(NBL,
                     __fmul_rn((float)(1.0 / 15.0),
                               __fdiv_rn(__fsub_rn(conf, BL), 0.2666666667f)));
    const float thr = nc - TOL;            // guidance only

    // ---- predict crossing index jp via secant on y(u)=log(S(u)-1), u in {6,12}.
    // ct(j) ~ 1/S(u_j); crossing where S = 1/thr. Prediction affects ONLY probe
    // placement; every accept/reject uses the exact recipe below.
    int jp = 755;                          // prior mode fallback
    {
        float a6  = S6  - 1.0f;
        float a12 = S12 - 1.0f;
        float at  = __fdiv_rn(1.0f, fmaxf(thr, 1e-6f)) - 1.0f;
        if (a6 > 1e-30f && a12 > 1e-30f && at > 1e-30f) {
            float y1 = __logf(a6);
            float y2 = __logf(a12);
            float yt = __logf(at);
            float k  = (y2 - y1) * (1.0f / 6.0f);     // < 0 normally
            if (k < -1e-9f) {
                float ustar = 6.0f + (yt - y1) / k;
                if (ustar >= 1.0f && ustar <= 1e6f) {
                    float jpf = (1.0f - __frcp_rn(ustar)) * 800.0f;
                    int j = (int)ceilf(jpf);
                    if (j < 0) j = 0;
                    if (j > NT - 1) j = NT - 1;
                    jp = j;
                }
            }
        }
    }

    // ---- search: round 0 = predicted placement, later rounds = uniform stride.
    // ct(j) monotone non-decreasing in j (temps decrease, terms shrink, fixed
    // summation tree preserves order) => first-true index search.
    const float4* d4 = (const float4*)dsm;
    const int offtab[NW] = {-10, -3, -1, 0, 1, 2, 4, 9};   // strictly ascending

    int lo = 0, hi = NT;       // hi == NT means "no true index found yet"
    float ct_hi = 0.0f;        // ct at index hi (valid when hi < NT)
    int par = 0, iter = 0;

    while (lo < hi) {
        const int range = hi - lo;
        const bool pred = (iter == 0);               // range==800 >= NW here
        const int stride = (range + NW - 1) >> 3;    // ceil(range/8) >= 1

        int pos; bool active;
        if (pred) {
            int x = jp + offtab[w];
            int a = lo + w, bnd = hi - NW + w;       // keeps positions strictly ascending
            pos = (x < a) ? a : ((x > bnd) ? bnd : x);
            active = true;
        } else {
            pos = lo + w * stride;
            active = (pos < hi);
        }

        float ctv = 0.0f;
        if (active) {                                // warp-uniform branch
            float t    = __fsub_rn(1.0f, __fmul_rn(TSTEP, (float)pos));
            float invt = __frcp_rn(t);               // == __fdiv_rn(1, t)
            float a0 = 0.0f, a1 = 0.0f, a2 = 0.0f, a3 = 0.0f;
#pragma unroll
            for (int k = 0; k < 8; k++) {
                float4 v = d4[lane + k * 32];
                a0 += __expf(__fmul_rn(v.x, invt));
                a1 += __expf(__fmul_rn(v.y, invt));
                a2 += __expf(__fmul_rn(v.z, invt));
                a3 += __expf(__fmul_rn(v.w, invt));
            }
            float s = (a0 + a1) + (a2 + a3);
#pragma unroll
            for (int o = 16; o > 0; o >>= 1) s += __shfl_xor_sync(0xffffffffu, s, o);
            float mx  = __fmul_rn(m, invt);
            float lse = __fadd_rn(logf(s), mx);
            ctv = expf(__fsub_rn(mx, lse));          // reference rounding chain
        }
        if (lane == 0) ctbuf[par][w] = ctv;
        __syncthreads();   // single barrier per round (double-buffered ctbuf)

        // All threads redundantly (deterministically) update the interval.
        int first = -1, lastidx = 0;
        int posArr[NW];
#pragma unroll
        for (int i = 0; i < NW; i++) {
            int p; bool act;
            if (pred) {
                int x = jp + offtab[i];
                int a = lo + i, bnd = hi - NW + i;
                p = (x < a) ? a : ((x > bnd) ? bnd : x);
                act = true;
            } else {
                p = lo + i * stride;
                act = (p < hi);
            }
            posArr[i] = p;
            if (act) {
                lastidx = i;
                if (first < 0 && __fsub_rn(ctbuf[par][i], nc) >= -TOL) first = i;
            }
        }
        if (first >= 0) {
            ct_hi = ctbuf[par][first];
            hi = posArr[first];
            if (first > 0) lo = posArr[first - 1] + 1;
        } else {
            lo = posArr[lastidx] + 1;
        }
        par ^= 1;
        iter++;
    }

    // ---- band check + output ----
    bool found = false;
    float tj = 1.0f;
    if (hi < NT) {
        float g = __fsub_rn(ct_hi, nc);              // >= -TOL by construction
        found = (fabsf(g) <= TOL);
        tj = __fsub_rn(1.0f, __fmul_rn(TSTEP, (float)hi));
    }
#pragma unroll
    for (int k = 0; k < 4; k++) {
        int idx = tid + k * NTHREADS;
        if (idx < NCLS) orow[idx] = found ? __fdiv_rn(r[k], tj) : r[k];
    }
}

extern "C" void kernel_launch(void* const* d_in, const int* in_sizes, int n_in,
                              void* d_out, int out_size) {
    const float* logits = (const float*)d_in[0];
    float* out = (float*)d_out;
    int B = in_sizes[0] / NCLS;   // 128 rows
    logit_compression_kernel<<<B, NTHREADS>>>(logits, out);
}

// round 6
// speedup vs baseline: 1.0300x; 1.0300x over previous
#include <cuda_runtime.h>
#include <math.h>

#define NTHREADS 256
#define NW 8            // warps per block = probes per round
#define NCLS 1000
#define NPAD 1024
#define NT 800
#define TSTEP 0.00125f
#define TOL 0.01f

__global__ __launch_bounds__(NTHREADS)
void logit_compression_kernel(const float* __restrict__ logits,
                              float* __restrict__ out) {
    __shared__ float dsm[NPAD];      // d_j = fl(l_j - m), padded with -inf
    __shared__ float redm[NW];
    __shared__ float red1[NW];
    __shared__ float ctbuf[2][NW];

    const int tid  = threadIdx.x;
    const int lane = tid & 31;
    const int w    = tid >> 5;
    const int row  = blockIdx.x;
    const float* lrow = logits + row * NCLS;
    float* orow = out + row * NCLS;

    // ---- load row ----
    float r[4];
#pragma unroll
    for (int k = 0; k < 4; k++) {
        int idx = tid + k * NTHREADS;
        r[k] = (idx < NCLS) ? lrow[idx] : -INFINITY;
    }

    // ---- block max: warp reduce, then ALL threads combine 8 partials (fixed order) ----
    float mv = fmaxf(fmaxf(r[0], r[1]), fmaxf(r[2], r[3]));
#pragma unroll
    for (int o = 16; o > 0; o >>= 1) mv = fmaxf(mv, __shfl_xor_sync(0xffffffffu, mv, o));
    if (lane == 0) redm[w] = mv;
    __syncthreads();
    float m = redm[0];
#pragma unroll
    for (int i = 1; i < NW; i++) m = fmaxf(m, redm[i]);

    // ---- d -> smem; S1 with ACCURATE expf on exact d (reference-faithful) ----
    float s1 = 0.0f;
#pragma unroll
    for (int k = 0; k < 4; k++) {
        float dk = __fsub_rn(r[k], m);     // -inf for padding lanes
        dsm[tid + k * NTHREADS] = dk;
        s1 += expf(dk);                    // expf(-inf) == 0
    }
#pragma unroll
    for (int o = 16; o > 0; o >>= 1) s1 += __shfl_xor_sync(0xffffffffu, s1, o);
    if (lane == 0) red1[w] = s1;
    __syncthreads();                       // publishes red1 AND dsm to all warps
    const float S1 = ((red1[0] + red1[1]) + (red1[2] + red1[3]))
                   + ((red1[4] + red1[5]) + (red1[6] + red1[7]));

    // ---- original confidence, bin, target confidence (reference rounding) ----
    const float conf = __fdiv_rn(1.0f, S1);
    int b = (conf >= (2.0f / 3.0f)) ? 2 : (conf >= (1.0f / 3.0f)) ? 1 : 0;
    const float BL  = (b == 0) ? 0.0f : (b == 1) ? (1.0f / 3.0f) : (2.0f / 3.0f);
    const float NBL = (b == 0) ? 0.8f : (b == 1) ? 0.86666666666f : 0.93333333333f;
    const float nc  = __fadd_rn(NBL,
                     __fmul_rn((float)(1.0 / 15.0),
                               __fdiv_rn(__fsub_rn(conf, BL), 0.2666666667f)));

    // ---- parallel search for first j with ct(j) >= nc - TOL ----
    // ct(j) is monotone non-decreasing in j (temps decrease, every term
    // exp(d*u_j) shrinks, fixed summation tree preserves order).
    //
    // Round 0 uses a STRUCTURAL prior: nc >= 0.8 always (new_bin_lowers >= 0.8),
    // so ct must climb to ~0.79+, which for non-dominant-max rows means
    // u = 1/t >= ~9, i.e. j >= ~710. Probe densely there; rows that cross
    // earlier fall back to the uniform-stride rounds (still correct).
    const float4* d4 = (const float4*)dsm;
    const int P0[NW] = {520, 660, 712, 744, 764, 780, 792, 799};  // ascending

    int lo = 0, hi = NT;       // hi == NT means "no true index found yet"
    float ct_hi = 0.0f;        // ct at index hi (valid when hi < NT)
    int par = 0;
    bool tab = true;           // round 0 = table round

    while (lo < hi) {
        const int stride = (hi - lo + NW - 1) >> 3;   // ceil(range/8) >= 1
        int pos; bool active;
        if (tab) { pos = P0[w];          active = true; }
        else     { pos = lo + w * stride; active = (pos < hi); }

        float ctv = 0.0f;
        if (active) {                                 // warp-uniform branch
            float t    = __fsub_rn(1.0f, __fmul_rn(TSTEP, (float)pos));
            float invt = __frcp_rn(t);                // == __fdiv_rn(1, t)
            float a0 = 0.0f, a1 = 0.0f, a2 = 0.0f, a3 = 0.0f;
#pragma unroll
            for (int k = 0; k < 8; k++) {
                float4 v = d4[lane + k * 32];
                a0 += __expf(__fmul_rn(v.x, invt));
                a1 += __expf(__fmul_rn(v.y, invt));
                a2 += __expf(__fmul_rn(v.z, invt));
                a3 += __expf(__fmul_rn(v.w, invt));
            }
            float s = (a0 + a1) + (a2 + a3);
#pragma unroll
            for (int o = 16; o > 0; o >>= 1) s += __shfl_xor_sync(0xffffffffu, s, o);
            float mx  = __fmul_rn(m, invt);
            float lse = __fadd_rn(logf(s), mx);
            ctv = expf(__fsub_rn(mx, lse));           // reference rounding chain
        }
        if (lane == 0) ctbuf[par][w] = ctv;
        __syncthreads();   // single barrier per round (double-buffered ctbuf)

        // All threads redundantly (deterministically) update the interval.
        int first = -1, lastidx = 0;
        int pprev = 0, pfirst = 0, plast = 0;
#pragma unroll
        for (int i = 0; i < NW; i++) {
            int p  = tab ? P0[i] : (lo + i * stride);
            bool a = tab ? true  : (p < hi);
            if (a) {
                if (first < 0) {
                    if (__fsub_rn(ctbuf[par][i], nc) >= -TOL) { first = i; pfirst = p; }
                    else pprev = p;
                }
                lastidx = i; plast = p;
            }
        }
        if (first >= 0) {
            ct_hi = ctbuf[par][first];
            hi = pfirst;
            if (first > 0) lo = pprev + 1;
            // first == 0: lo unchanged (table round: crossing may be < P0[0])
        } else {
            lo = plast + 1;
        }
        (void)lastidx;
        par ^= 1;
        tab = false;
    }

    // ---- band check + output ----
    bool found = false;
    float tj = 1.0f;
    if (hi < NT) {
        float g = __fsub_rn(ct_hi, nc);               // >= -TOL by construction
        found = (fabsf(g) <= TOL);
        tj = __fsub_rn(1.0f, __fmul_rn(TSTEP, (float)hi));
    }
#pragma unroll
    for (int k = 0; k < 4; k++) {
        int idx = tid + k * NTHREADS;
        if (idx < NCLS) orow[idx] = found ? __fdiv_rn(r[k], tj) : r[k];
    }
}

extern "C" void kernel_launch(void* const* d_in, const int* in_sizes, int n_in,
                              void* d_out, int out_size) {
    const float* logits = (const float*)d_in[0];
    float* out = (float*)d_out;
    int B = in_sizes[0] / NCLS;   // 128 rows
    logit_compression_kernel<<<B, NTHREADS>>>(logits, out);
}

// round 7
// speedup vs baseline: 1.2294x; 1.1935x over previous
#include <cuda_runtime.h>
#include <math.h>

#define NTHREADS 256
#define NW 8            // warps per block = probes per round
#define NCLS 1000
#define NPAD 1024
#define NT 800
#define TSTEP 0.00125f
#define TOL 0.01f

__device__ __forceinline__ float ex2(float x) {
    float y;
    asm("ex2.approx.f32 %0, %1;" : "=f"(y) : "f"(x));
    return y;
}

__global__ __launch_bounds__(NTHREADS)
void logit_compression_kernel(const float* __restrict__ logits,
                              float* __restrict__ out) {
    __shared__ float dsm[NPAD];      // d_j = fl(l_j - m), padded with -inf
    __shared__ float redm[NW];
    __shared__ float red1[NW];
    __shared__ float ctbuf[2][NW];

    const int tid  = threadIdx.x;
    const int lane = tid & 31;
    const int w    = tid >> 5;
    const int row  = blockIdx.x;
    const float* lrow = logits + row * NCLS;
    float* orow = out + row * NCLS;

    // ---- load row ----
    float r[4];
#pragma unroll
    for (int k = 0; k < 4; k++) {
        int idx = tid + k * NTHREADS;
        r[k] = (idx < NCLS) ? lrow[idx] : -INFINITY;
    }

    // ---- block max: warp reduce, then all threads combine 8 partials (fixed order) ----
    float mv = fmaxf(fmaxf(r[0], r[1]), fmaxf(r[2], r[3]));
#pragma unroll
    for (int o = 16; o > 0; o >>= 1) mv = fmaxf(mv, __shfl_xor_sync(0xffffffffu, mv, o));
    if (lane == 0) redm[w] = mv;
    __syncthreads();
    float m = redm[0];
#pragma unroll
    for (int i = 1; i < NW; i++) m = fmaxf(m, redm[i]);

    // ---- d -> smem; S1 with ACCURATE expf on exact d (decision-critical for conf) ----
    float s1 = 0.0f;
#pragma unroll
    for (int k = 0; k < 4; k++) {
        float dk = __fsub_rn(r[k], m);     // -inf for padding lanes
        dsm[tid + k * NTHREADS] = dk;
        s1 += expf(dk);                    // expf(-inf) == 0
    }
#pragma unroll
    for (int o = 16; o > 0; o >>= 1) s1 += __shfl_xor_sync(0xffffffffu, s1, o);
    if (lane == 0) red1[w] = s1;
    __syncthreads();                       // publishes red1 AND dsm to all warps
    const float S1 = ((red1[0] + red1[1]) + (red1[2] + red1[3]))
                   + ((red1[4] + red1[5]) + (red1[6] + red1[7]));

    // ---- original confidence, bin, target confidence (reference rounding) ----
    const float conf = __fdiv_rn(1.0f, S1);
    int b = (conf >= (2.0f / 3.0f)) ? 2 : (conf >= (1.0f / 3.0f)) ? 1 : 0;
    const float BL  = (b == 0) ? 0.0f : (b == 1) ? (1.0f / 3.0f) : (2.0f / 3.0f);
    const float NBL = (b == 0) ? 0.8f : (b == 1) ? 0.86666666666f : 0.93333333333f;
    const float nc  = __fadd_rn(NBL,
                     __fmul_rn((float)(1.0 / 15.0),
                               __fdiv_rn(__fsub_rn(conf, BL), 0.2666666667f)));

    // ---- parallel search for first j with ct(j) >= nc - TOL ----
    // ct(j) = 1/S(u_j) monotone non-decreasing in j (temps decrease, every
    // term exp2(d*c) shrinks, fixed summation tree preserves order).
    // Round 0 table = structural prior (nc >= 0.8 always => late crossings);
    // early-crossing rows fall back to the uniform-stride rounds.
    const float4* d4 = (const float4*)dsm;
    const int P0[NW] = {480, 600, 672, 720, 752, 776, 792, 799};  // ascending

    int lo = 0, hi = NT;       // hi == NT means "no true index found yet"
    float ct_hi = 0.0f;        // ct at index hi (valid when hi < NT)
    int par = 0;
    bool tab = true;           // round 0 = table round

    while (lo < hi) {
        const int stride = (hi - lo + NW - 1) >> 3;   // ceil(range/8) >= 1
        int pos; bool active;
        if (tab) { pos = P0[w];           active = true; }
        else     { pos = lo + w * stride; active = (pos < hi); }

        float ctv = 0.0f;
        if (active) {                                 // warp-uniform branch
            float t    = __fsub_rn(1.0f, __fmul_rn(TSTEP, (float)pos));
            float invt = __frcp_rn(t);
            float c2   = __fmul_rn(invt, 1.4426950408889634f);  // log2(e)/t
            float a0 = 0.0f, a1 = 0.0f, a2 = 0.0f, a3 = 0.0f;
#pragma unroll
            for (int k = 0; k < 8; k++) {
                float4 v = d4[lane + k * 32];
                a0 += ex2(__fmul_rn(v.x, c2));
                a1 += ex2(__fmul_rn(v.y, c2));
                a2 += ex2(__fmul_rn(v.z, c2));
                a3 += ex2(__fmul_rn(v.w, c2));
            }
            float s = (a0 + a1) + (a2 + a3);
#pragma unroll
            for (int o = 16; o > 0; o >>= 1) s += __shfl_xor_sync(0xffffffffu, s, o);
            ctv = __frcp_rn(s);            // ct = 1/S (== exp(mx - lse) to ~1e-7)
        }
        if (lane == 0) ctbuf[par][w] = ctv;
        __syncthreads();   // single barrier per round (double-buffered ctbuf)

        // All threads redundantly (deterministically) update the interval.
        int first = -1;
        int pprev = 0, pfirst = 0, plast = 0;
#pragma unroll
        for (int i = 0; i < NW; i++) {
            int p  = tab ? P0[i] : (lo + i * stride);
            bool a = tab ? true  : (p < hi);
            if (a) {
                if (first < 0) {
                    if (__fsub_rn(ctbuf[par][i], nc) >= -TOL) { first = i; pfirst = p; }
                    else pprev = p;
                }
                plast = p;
            }
        }
        if (first >= 0) {
            ct_hi = ctbuf[par][first];
            hi = pfirst;
            if (first > 0) lo = pprev + 1;
            // first == 0: lo unchanged (table round: crossing may be < P0[0])
        } else {
            lo = plast + 1;
        }
        par ^= 1;
        tab = false;
    }

    // ---- band check + output ----
    bool found = false;
    float tj = 1.0f;
    if (hi < NT) {
        float g = __fsub_rn(ct_hi, nc);               // >= -TOL by construction
        found = (fabsf(g) <= TOL);
        tj = __fsub_rn(1.0f, __fmul_rn(TSTEP, (float)hi));
    }
#pragma unroll
    for (int k = 0; k < 4; k++) {
        int idx = tid + k * NTHREADS;
        if (idx < NCLS) orow[idx] = found ? __fdiv_rn(r[k], tj) : r[k];
    }
}

extern "C" void kernel_launch(void* const* d_in, const int* in_sizes, int n_in,
                              void* d_out, int out_size) {
    const float* logits = (const float*)d_in[0];
    float* out = (float*)d_out;
    int B = in_sizes[0] / NCLS;   // 128 rows
    logit_compression_kernel<<<B, NTHREADS>>>(logits, out);
}